// round 12
// baseline (speedup 1.0000x reference)
#include <cuda_runtime.h>
#include <cuda_fp16.h>
#include <math.h>

// Problem constants
#define BB 8
#define TT 1024
#define CC 768
#define NH 12
#define HD 64
#define C3 (3*CC)   // 2304

#define LOG2E 1.4426950408889634f

// ---------------- scratch (no allocation allowed) ----------------
__device__ __half g_qkvh[BB * TT * C3];  // fp16 qkv
__device__ __half g_yh  [BB * TT * CC];  // fp16 attention output
__device__ __half g_xh  [BB * TT * CC];  // fp16 x
__device__ __half g_wah [CC * C3];       // fp16 W_attn
__device__ __half g_wph [CC * CC];       // fp16 W_proj

__device__ __forceinline__ void cp_async16(void* smem, const void* gmem) {
    unsigned s = (unsigned)__cvta_generic_to_shared(smem);
    asm volatile("cp.async.cg.shared.global [%0], [%1], 16;\n" :: "r"(s), "l"(gmem));
}

__device__ __forceinline__ float ex2f(float x) {
    float r; asm("ex2.approx.f32 %0, %1;" : "=f"(r) : "f"(x)); return r;
}
__device__ __forceinline__ unsigned h2ex2(unsigned x) {
    unsigned r; asm("ex2.approx.f16x2 %0, %1;" : "=r"(r) : "r"(x)); return r;
}
__device__ __forceinline__ unsigned pack_h2(float lo, float hi) {
    __half2 h = __floats2half2_rn(lo, hi);
    return *reinterpret_cast<unsigned*>(&h);
}

#define MMA_F16(acc, a, b0v, b1v)                                               \
    asm volatile(                                                               \
        "mma.sync.aligned.m16n8k16.row.col.f32.f16.f16.f32 "                    \
        "{%0,%1,%2,%3}, {%4,%5,%6,%7}, {%8,%9}, {%0,%1,%2,%3};"                 \
        : "+f"(acc[0]), "+f"(acc[1]), "+f"(acc[2]), "+f"(acc[3])                \
        : "r"(a[0]), "r"(a[1]), "r"(a[2]), "r"(a[3]), "r"(b0v), "r"(b1v))

#define LDSM_X4(r, addr)                                                        \
    asm volatile("ldmatrix.sync.aligned.m8n8.x4.shared.b16 {%0,%1,%2,%3}, [%4];"\
        : "=r"((r)[0]), "=r"((r)[1]), "=r"((r)[2]), "=r"((r)[3]) : "r"(addr))

#define LDSM_X4_T(r, addr)                                                      \
    asm volatile("ldmatrix.sync.aligned.m8n8.x4.trans.shared.b16 {%0,%1,%2,%3}, [%4];"\
        : "=r"((r)[0]), "=r"((r)[1]), "=r"((r)[2]), "=r"((r)[3]) : "r"(addr))

// ---------------- merged pre-pass: fp32 -> fp16 for x, W_attn, W_proj ----------------
#define NX8 (BB * TT * CC / 8)   // 786432
#define NA8 (CC * C3 / 8)        // 221184
#define NP8 (CC * CC / 8)        // 73728

__global__ __launch_bounds__(256)
void prep_f16_kernel(const float* __restrict__ x,  const float* __restrict__ wa,
                     const float* __restrict__ wp,
                     __half* __restrict__ xh, __half* __restrict__ wah,
                     __half* __restrict__ wph)
{
    int i = blockIdx.x * blockDim.x + threadIdx.x;
    const float* in; __half* out;
    if (i < NX8)             { in = x;  out = xh;  }
    else if (i < NX8 + NA8)  { in = wa; out = wah; i -= NX8; }
    else if (i < NX8 + NA8 + NP8) { in = wp; out = wph; i -= NX8 + NA8; }
    else return;
    const float4 v0 = reinterpret_cast<const float4*>(in)[2*i];
    const float4 v1 = reinterpret_cast<const float4*>(in)[2*i + 1];
    __half2 h[4];
    h[0] = __floats2half2_rn(v0.x, v0.y);
    h[1] = __floats2half2_rn(v0.z, v0.w);
    h[2] = __floats2half2_rn(v1.x, v1.y);
    h[3] = __floats2half2_rn(v1.z, v1.w);
    reinterpret_cast<uint4*>(out)[i] = *reinterpret_cast<uint4*>(h);
}

// ================= fp16 tensor-core GEMM, BN=128 (QKV) =================
#define BM 128
#define BN 128
#define BK 32
#define AS_STR 40
#define BS_STR 136

__global__ __launch_bounds__(256, 2)
void h16_gemm_bias_n128(const __half* __restrict__ A,
                        const __half* __restrict__ W,
                        const float* __restrict__ bias,
                        __half* __restrict__ Cout,
                        int M, int N, int K)
{
    __shared__ __half As[2][BM][AS_STR];
    __shared__ __half Bs[2][BK][BS_STR];

    const int tid  = threadIdx.x;
    const int lane = tid & 31;
    const int warp = tid >> 5;
    const int wm   = warp >> 2;
    const int wn   = warp & 3;
    const int grp  = lane >> 2;
    const int qd   = lane & 3;
    const int m0   = blockIdx.y * BM;
    const int n0   = blockIdx.x * BN;

    const int a_row = tid >> 2;
    const int a_col = (tid & 3) * 8;
    const int b_row = tid >> 4;
    const int b_col = (tid & 15) * 8;

    const unsigned as_base = (unsigned)__cvta_generic_to_shared(&As[0][0][0]);
    const unsigned bs_base = (unsigned)__cvta_generic_to_shared(&Bs[0][0][0]);
    const int rk_row = (lane & 7) + ((lane >> 3) & 1) * 8;
    const int rk_col = (lane >> 4) * 8;

    float acc[4][4][4] = {};

    auto load_tile = [&](int buf, int k0) {
        cp_async16(&As[buf][a_row     ][a_col], &A[(size_t)(m0 + a_row     ) * K + k0 + a_col]);
        cp_async16(&As[buf][a_row + 64][a_col], &A[(size_t)(m0 + a_row + 64) * K + k0 + a_col]);
        cp_async16(&Bs[buf][b_row     ][b_col], &W[(size_t)(k0 + b_row     ) * N + n0 + b_col]);
        cp_async16(&Bs[buf][b_row + 16][b_col], &W[(size_t)(k0 + b_row + 16) * N + n0 + b_col]);
        asm volatile("cp.async.commit_group;\n");
    };

    const int nk = K / BK;
    load_tile(0, 0);
    asm volatile("cp.async.wait_group 0;\n");
    __syncthreads();

    for (int t = 0; t < nk; t++) {
        const int buf = t & 1;
        if (t + 1 < nk) load_tile(buf ^ 1, (t + 1) * BK);

        #pragma unroll
        for (int ks = 0; ks < BK; ks += 16) {
            unsigned afr[4][4], bfr[2][4];
            #pragma unroll
            for (int mt = 0; mt < 4; mt++) {
                const unsigned addr = as_base +
                    (unsigned)(((buf * BM + wm * 64 + mt * 16 + rk_row) * AS_STR
                                + ks + rk_col) * 2);
                LDSM_X4(afr[mt], addr);
            }
            #pragma unroll
            for (int nh = 0; nh < 2; nh++) {
                const unsigned addr = bs_base +
                    (unsigned)(((buf * BK + ks + rk_row) * BS_STR
                                + wn * 32 + nh * 16 + rk_col) * 2);
                LDSM_X4_T(bfr[nh], addr);
            }
            #pragma unroll
            for (int mt = 0; mt < 4; mt++)
                #pragma unroll
                for (int nt = 0; nt < 4; nt++) {
                    const int nh = nt >> 1, lo = (nt & 1) * 2;
                    MMA_F16(acc[mt][nt], afr[mt], bfr[nh][lo], bfr[nh][lo + 1]);
                }
        }

        if (t + 1 < nk) asm volatile("cp.async.wait_group 0;\n");
        __syncthreads();
    }

    #pragma unroll
    for (int mt = 0; mt < 4; mt++) {
        const int r = m0 + wm * 64 + mt * 16 + grp;
        #pragma unroll
        for (int nt = 0; nt < 4; nt++) {
            const int c = n0 + wn * 32 + nt * 8 + qd * 2;
            const float2 bi = *reinterpret_cast<const float2*>(&bias[c]);
            *reinterpret_cast<__half2*>(&Cout[(size_t)r       * N + c]) =
                __floats2half2_rn(acc[mt][nt][0] + bi.x, acc[mt][nt][1] + bi.y);
            *reinterpret_cast<__half2*>(&Cout[(size_t)(r + 8) * N + c]) =
                __floats2half2_rn(acc[mt][nt][2] + bi.x, acc[mt][nt][3] + bi.y);
        }
    }
}

// ================= fp16 tensor-core GEMM, BN=64 / occ-3 (proj) =================
// Warp tile 64x16 -> acc 32 regs; target 3 CTAs/SM to pack grid 768 into ~1.7 waves.
#define BS_STR64 72

__global__ __launch_bounds__(256, 3)
void h16_gemm_bias_n64(const __half* __restrict__ A,
                       const __half* __restrict__ W,
                       const float* __restrict__ bias,
                       float* __restrict__ Cout,
                       int M, int N, int K)
{
    __shared__ __half As[2][BM][AS_STR];
    __shared__ __half Bs[2][BK][BS_STR64];

    const int tid  = threadIdx.x;
    const int lane = tid & 31;
    const int warp = tid >> 5;
    const int wm   = warp >> 2;          // 0..1 -> 64 rows
    const int wn   = warp & 3;           // 0..3 -> 16 cols
    const int grp  = lane >> 2;
    const int qd   = lane & 3;
    const int m0   = blockIdx.y * BM;
    const int n0   = blockIdx.x * 64;

    const int a_row = tid >> 2;
    const int a_col = (tid & 3) * 8;
    const int b_row = tid >> 3;          // 0..31
    const int b_col = (tid & 7) * 8;     // 0..56

    const unsigned as_base = (unsigned)__cvta_generic_to_shared(&As[0][0][0]);
    const unsigned bs_base = (unsigned)__cvta_generic_to_shared(&Bs[0][0][0]);
    const int rk_row = (lane & 7) + ((lane >> 3) & 1) * 8;
    const int rk_col = (lane >> 4) * 8;

    float acc[4][2][4] = {};

    auto load_tile = [&](int buf, int k0) {
        cp_async16(&As[buf][a_row     ][a_col], &A[(size_t)(m0 + a_row     ) * K + k0 + a_col]);
        cp_async16(&As[buf][a_row + 64][a_col], &A[(size_t)(m0 + a_row + 64) * K + k0 + a_col]);
        cp_async16(&Bs[buf][b_row][b_col], &W[(size_t)(k0 + b_row) * N + n0 + b_col]);
        asm volatile("cp.async.commit_group;\n");
    };

    const int nk = K / BK;
    load_tile(0, 0);
    asm volatile("cp.async.wait_group 0;\n");
    __syncthreads();

    for (int t = 0; t < nk; t++) {
        const int buf = t & 1;
        if (t + 1 < nk) load_tile(buf ^ 1, (t + 1) * BK);

        #pragma unroll
        for (int ks = 0; ks < BK; ks += 16) {
            unsigned afr[4][4], bfr[4];
            #pragma unroll
            for (int mt = 0; mt < 4; mt++) {
                const unsigned addr = as_base +
                    (unsigned)(((buf * BM + wm * 64 + mt * 16 + rk_row) * AS_STR
                                + ks + rk_col) * 2);
                LDSM_X4(afr[mt], addr);
            }
            {
                const unsigned addr = bs_base +
                    (unsigned)(((buf * BK + ks + rk_row) * BS_STR64
                                + wn * 16 + rk_col) * 2);
                LDSM_X4_T(bfr, addr);
            }
            #pragma unroll
            for (int mt = 0; mt < 4; mt++)
                #pragma unroll
                for (int nt = 0; nt < 2; nt++)
                    MMA_F16(acc[mt][nt], afr[mt], bfr[nt * 2], bfr[nt * 2 + 1]);
        }

        if (t + 1 < nk) asm volatile("cp.async.wait_group 0;\n");
        __syncthreads();
    }

    #pragma unroll
    for (int mt = 0; mt < 4; mt++) {
        const int r = m0 + wm * 64 + mt * 16 + grp;
        #pragma unroll
        for (int nt = 0; nt < 2; nt++) {
            const int c = n0 + wn * 16 + nt * 8 + qd * 2;
            const float2 bi = *reinterpret_cast<const float2*>(&bias[c]);
            *reinterpret_cast<float2*>(&Cout[(size_t)r       * N + c]) =
                make_float2(acc[mt][nt][0] + bi.x, acc[mt][nt][1] + bi.y);
            *reinterpret_cast<float2*>(&Cout[(size_t)(r + 8) * N + c]) =
                make_float2(acc[mt][nt][2] + bi.x, acc[mt][nt][3] + bi.y);
        }
    }
}

// ================= fp16 flash attention: paired q-blocks, register-resident P =================
#define FBQ  128
#define FBKV 64
#define NQB  (TT / FBQ)    // 8
#define KS_STR 72
#define VS_STR 72
#define QS_STR 72

#define OFF_K 0
#define OFF_V (2 * FBKV * KS_STR)
#define OFF_Q (OFF_V + 2 * FBKV * VS_STR)
#define FLASH_SMEM_HALFS (OFF_Q + FBQ * QS_STR)
#define FLASH_SMEM_BYTES (FLASH_SMEM_HALFS * 2)    // 55296

#define ONES_H2 0x3C003C00u

__global__ __launch_bounds__(256)
void flash_attn_h16(const __half* __restrict__ qkv, __half* __restrict__ y)
{
    extern __shared__ __half hsm[];
    __half* KsBase = hsm + OFF_K;
    __half* VsBase = hsm + OFF_V;
    __half* Qsm    = hsm + OFF_Q;

    const int tid  = threadIdx.x;
    const int lane = tid & 31;
    const int warp = tid >> 5;
    const int g8   = lane >> 2;
    const int qd   = lane & 3;
    const int h    = blockIdx.y;
    const int b    = blockIdx.z;
    const int wb   = warp * 16;

    const unsigned k_sbase = (unsigned)__cvta_generic_to_shared(KsBase);
    const unsigned v_sbase = (unsigned)__cvta_generic_to_shared(VsBase);
    const unsigned q_sbase = (unsigned)__cvta_generic_to_shared(Qsm);

    const int rk_row = (lane & 7) + ((lane >> 3) & 1) * 8;
    const int rk_col = (lane >> 4) * 8;
    const int bn_row = (lane & 7) + (lane >> 4) * 8;
    const int bn_col = ((lane >> 3) & 1) * 8;

    const __half* base = qkv + (size_t)b * TT * C3 + h * HD;

    auto load_kv = [&](int bf, int kt) {
        const int r = tid >> 2;
        const int c = (tid & 3) * 16;
        __half* Kd = KsBase + bf * (FBKV * KS_STR);
        __half* Vd = VsBase + bf * (FBKV * VS_STR);
        const __half* rowp = base + (size_t)(kt + r) * C3;
        cp_async16(&Kd[r * KS_STR + c    ], rowp + CC   + c);
        cp_async16(&Kd[r * KS_STR + c + 8], rowp + CC   + c + 8);
        cp_async16(&Vd[r * VS_STR + c    ], rowp + 2*CC + c);
        cp_async16(&Vd[r * VS_STR + c + 8], rowp + 2*CC + c + 8);
        asm volatile("cp.async.commit_group;\n");
    };

    #pragma unroll 1
    for (int pass = 0; pass < 2; pass++) {
        const int qb = (pass == 0) ? (int)blockIdx.x : (NQB - 1 - (int)blockIdx.x);
        const int q0 = qb * FBQ;

        // ---- stage Q ----
        {
            const int r = tid >> 2;
            const int c = (tid & 3) * 16;
            cp_async16(&Qsm[(r     ) * QS_STR + c    ], &base[(size_t)(q0 + r     ) * C3 + c    ]);
            cp_async16(&Qsm[(r     ) * QS_STR + c + 8], &base[(size_t)(q0 + r     ) * C3 + c + 8]);
            cp_async16(&Qsm[(r + 64) * QS_STR + c    ], &base[(size_t)(q0 + r + 64) * C3 + c    ]);
            cp_async16(&Qsm[(r + 64) * QS_STR + c + 8], &base[(size_t)(q0 + r + 64) * C3 + c + 8]);
        }

        float m_i[2] = {-1e30f, -1e30f};
        float l_i[2] = {0.f, 0.f};
        float O[8][4] = {};
        unsigned qfr[4][4];

        const int ntiles = (q0 + FBQ) / FBKV;
        load_kv(0, 0);   // commits Q staging + first K/V together

        for (int t = 0; t < ntiles; t++) {
            const int buf = t & 1;
            const int kt  = t * FBKV;
            asm volatile("cp.async.wait_group 0;\n");
            __syncthreads();

            if (t == 0) {
                const __half2 sc2 = __floats2half2_rn(0.125f, 0.125f);
                #pragma unroll
                for (int ks = 0; ks < 4; ks++) {
                    const unsigned addr = q_sbase +
                        (unsigned)(((wb + rk_row) * QS_STR + ks * 16 + rk_col) * 2);
                    LDSM_X4(qfr[ks], addr);
                    #pragma unroll
                    for (int j = 0; j < 4; j++) {
                        __half2 hv = *reinterpret_cast<__half2*>(&qfr[ks][j]);
                        hv = __hmul2(hv, sc2);
                        qfr[ks][j] = *reinterpret_cast<unsigned*>(&hv);
                    }
                }
            }
            if (t + 1 < ntiles) load_kv(buf ^ 1, kt + FBKV);

            const unsigned kb_off = k_sbase + (unsigned)(buf * (FBKV * KS_STR) * 2);
            const unsigned vb_off = v_sbase + (unsigned)(buf * (FBKV * VS_STR) * 2);

            // ---- S = Q @ K^T ----
            float scf[8][4] = {};
            #pragma unroll
            for (int ks = 0; ks < 4; ks++) {
                #pragma unroll
                for (int ntp = 0; ntp < 4; ntp++) {
                    unsigned kb[4];
                    const unsigned addr = kb_off +
                        (unsigned)(((ntp * 16 + bn_row) * KS_STR + ks * 16 + bn_col) * 2);
                    LDSM_X4(kb, addr);
                    MMA_F16(scf[2*ntp    ], qfr[ks], kb[0], kb[1]);
                    MMA_F16(scf[2*ntp + 1], qfr[ks], kb[2], kb[3]);
                }
            }

            // ---- causal mask (diagonal tiles only) ----
            if (kt + FBKV > q0) {
                const int r0g = q0 + wb + g8;
                const int r1g = r0g + 8;
                #pragma unroll
                for (int nt = 0; nt < 8; nt++) {
                    const int c0 = kt + nt * 8 + 2 * qd;
                    if (c0     > r0g) scf[nt][0] = -1e30f;
                    if (c0 + 1 > r0g) scf[nt][1] = -1e30f;
                    if (c0     > r1g) scf[nt][2] = -1e30f;
                    if (c0 + 1 > r1g) scf[nt][3] = -1e30f;
                }
            }

            // ---- row max ----
            float mx0 = -1e30f, mx1 = -1e30f;
            #pragma unroll
            for (int nt = 0; nt < 8; nt++) {
                mx0 = fmaxf(mx0, fmaxf(scf[nt][0], scf[nt][1]));
                mx1 = fmaxf(mx1, fmaxf(scf[nt][2], scf[nt][3]));
            }
            #pragma unroll
            for (int off = 1; off <= 2; off <<= 1) {
                mx0 = fmaxf(mx0, __shfl_xor_sync(0xffffffffu, mx0, off));
                mx1 = fmaxf(mx1, __shfl_xor_sync(0xffffffffu, mx1, off));
            }
            const float mn0 = fmaxf(m_i[0], mx0);
            const float mn1 = fmaxf(m_i[1], mx1);
            const float mn0L = mn0 * LOG2E;
            const float mn1L = mn1 * LOG2E;
            const float cr0 = ex2f(fmaf(m_i[0], LOG2E, -mn0L));
            const float cr1 = ex2f(fmaf(m_i[1], LOG2E, -mn1L));
            m_i[0] = mn0; m_i[1] = mn1;

            // ---- P = exp2(S·log2e − m·log2e), built DIRECTLY as PV A-fragments ----
            unsigned pfr[4][4];
            #pragma unroll
            for (int ks = 0; ks < 4; ks++) {
                pfr[ks][0] = h2ex2(pack_h2(fmaf(scf[2*ks  ][0], LOG2E, -mn0L),
                                           fmaf(scf[2*ks  ][1], LOG2E, -mn0L)));
                pfr[ks][1] = h2ex2(pack_h2(fmaf(scf[2*ks  ][2], LOG2E, -mn1L),
                                           fmaf(scf[2*ks  ][3], LOG2E, -mn1L)));
                pfr[ks][2] = h2ex2(pack_h2(fmaf(scf[2*ks+1][0], LOG2E, -mn0L),
                                           fmaf(scf[2*ks+1][1], LOG2E, -mn0L)));
                pfr[ks][3] = h2ex2(pack_h2(fmaf(scf[2*ks+1][2], LOG2E, -mn1L),
                                           fmaf(scf[2*ks+1][3], LOG2E, -mn1L)));
            }

            // ---- O *= corr ----
            #pragma unroll
            for (int nt = 0; nt < 8; nt++) {
                O[nt][0] *= cr0; O[nt][1] *= cr0;
                O[nt][2] *= cr1; O[nt][3] *= cr1;
            }

            // ---- O += P @ V ; row sums l via ones-column MMA ----
            float lacc[4] = {0.f, 0.f, 0.f, 0.f};
            #pragma unroll
            for (int ks = 0; ks < 4; ks++) {
                MMA_F16(lacc, pfr[ks], ONES_H2, ONES_H2);
                #pragma unroll
                for (int nh = 0; nh < 4; nh++) {
                    unsigned vb[4];
                    const unsigned vaddr = vb_off +
                        (unsigned)(((ks * 16 + rk_row) * VS_STR + nh * 16 + rk_col) * 2);
                    LDSM_X4_T(vb, vaddr);
                    MMA_F16(O[2*nh    ], pfr[ks], vb[0], vb[1]);
                    MMA_F16(O[2*nh + 1], pfr[ks], vb[2], vb[3]);
                }
            }
            l_i[0] = l_i[0] * cr0 + lacc[0];
            l_i[1] = l_i[1] * cr1 + lacc[2];
        }

        // ---- epilogue for this q-block ----
        const float inv0 = 1.f / l_i[0];
        const float inv1 = 1.f / l_i[1];
        const size_t r0 = (size_t)b * TT + q0 + wb + g8;
        const size_t r1 = r0 + 8;
        #pragma unroll
        for (int nt = 0; nt < 8; nt++) {
            const int c = h * HD + nt * 8 + 2 * qd;
            *reinterpret_cast<__half2*>(&y[r0 * CC + c]) =
                __floats2half2_rn(O[nt][0] * inv0, O[nt][1] * inv0);
            *reinterpret_cast<__half2*>(&y[r1 * CC + c]) =
                __floats2half2_rn(O[nt][2] * inv1, O[nt][3] * inv1);
        }

        __syncthreads();   // smem safe to reuse for second pass
    }
}

// ---------------- launch ----------------
extern "C" void kernel_launch(void* const* d_in, const int* in_sizes, int n_in,
                              void* d_out, int out_size)
{
    const float* x      = (const float*)d_in[0];
    const float* W_attn = (const float*)d_in[1];
    const float* b_attn = (const float*)d_in[2];
    const float* W_proj = (const float*)d_in[3];
    const float* b_proj = (const float*)d_in[4];
    float* out = (float*)d_out;

    __half *qkvh, *yh, *xh, *wah, *wph;
    cudaGetSymbolAddress((void**)&qkvh, g_qkvh);
    cudaGetSymbolAddress((void**)&yh,   g_yh);
    cudaGetSymbolAddress((void**)&xh,   g_xh);
    cudaGetSymbolAddress((void**)&wah,  g_wah);
    cudaGetSymbolAddress((void**)&wph,  g_wph);

    cudaFuncSetAttribute(flash_attn_h16,
                         cudaFuncAttributeMaxDynamicSharedMemorySize,
                         FLASH_SMEM_BYTES);

    const int M = BB * TT;   // 8192

    // 0) convert inputs to fp16 (single merged launch)
    {
        const int ntot = NX8 + NA8 + NP8;
        prep_f16_kernel<<<(ntot + 255) / 256, 256>>>(x, W_attn, W_proj, xh, wah, wph);
    }
    // 1) qkv = xh @ wah + b_attn (fp16 out)
    {
        dim3 grid(C3 / BN, M / BM);        // (18, 64)
        h16_gemm_bias_n128<<<grid, 256>>>(xh, wah, b_attn, qkvh, M, C3, CC);
    }
    // 2) flash attention -> yh (paired q-blocks, register P)
    {
        dim3 grid(TT / FBQ / 2, NH, BB);   // (4, 12, 8)
        flash_attn_h16<<<grid, 256, FLASH_SMEM_BYTES>>>(qkvh, yh);
    }
    // 3) out = yh @ wph + b_proj (fp32 out; BN=64 occ-3 variant for wave packing)
    {
        dim3 grid(CC / 64, M / BM);        // (12, 64)
        h16_gemm_bias_n64<<<grid, 256>>>(yh, wph, b_proj, out, M, CC, CC);
    }
}

// round 13
// speedup vs baseline: 1.0422x; 1.0422x over previous
#include <cuda_runtime.h>
#include <cuda_fp16.h>
#include <math.h>

// Problem constants
#define BB 8
#define TT 1024
#define CC 768
#define NH 12
#define HD 64
#define C3 (3*CC)   // 2304

#define LOG2E 1.4426950408889634f

// ---------------- scratch (no allocation allowed) ----------------
__device__ __half g_qkvh[BB * TT * C3];  // fp16 qkv
__device__ __half g_yh  [BB * TT * CC];  // fp16 attention output
__device__ __half g_xh  [BB * TT * CC];  // fp16 x
__device__ __half g_wah [CC * C3];       // fp16 W_attn
__device__ __half g_wph [CC * CC];       // fp16 W_proj

__device__ __forceinline__ void cp_async16(void* smem, const void* gmem) {
    unsigned s = (unsigned)__cvta_generic_to_shared(smem);
    asm volatile("cp.async.cg.shared.global [%0], [%1], 16;\n" :: "r"(s), "l"(gmem));
}

__device__ __forceinline__ float ex2f(float x) {
    float r; asm("ex2.approx.f32 %0, %1;" : "=f"(r) : "f"(x)); return r;
}
__device__ __forceinline__ unsigned h2ex2(unsigned x) {
    unsigned r; asm("ex2.approx.f16x2 %0, %1;" : "=r"(r) : "r"(x)); return r;
}
__device__ __forceinline__ unsigned pack_h2(float lo, float hi) {
    __half2 h = __floats2half2_rn(lo, hi);
    return *reinterpret_cast<unsigned*>(&h);
}

#define MMA_F16(acc, a, b0v, b1v)                                               \
    asm volatile(                                                               \
        "mma.sync.aligned.m16n8k16.row.col.f32.f16.f16.f32 "                    \
        "{%0,%1,%2,%3}, {%4,%5,%6,%7}, {%8,%9}, {%0,%1,%2,%3};"                 \
        : "+f"(acc[0]), "+f"(acc[1]), "+f"(acc[2]), "+f"(acc[3])                \
        : "r"(a[0]), "r"(a[1]), "r"(a[2]), "r"(a[3]), "r"(b0v), "r"(b1v))

#define LDSM_X4(r, addr)                                                        \
    asm volatile("ldmatrix.sync.aligned.m8n8.x4.shared.b16 {%0,%1,%2,%3}, [%4];"\
        : "=r"((r)[0]), "=r"((r)[1]), "=r"((r)[2]), "=r"((r)[3]) : "r"(addr))

#define LDSM_X4_T(r, addr)                                                      \
    asm volatile("ldmatrix.sync.aligned.m8n8.x4.trans.shared.b16 {%0,%1,%2,%3}, [%4];"\
        : "=r"((r)[0]), "=r"((r)[1]), "=r"((r)[2]), "=r"((r)[3]) : "r"(addr))

// ---------------- merged pre-pass: fp32 -> fp16 for x, W_attn, W_proj ----------------
#define NX8 (BB * TT * CC / 8)   // 786432
#define NA8 (CC * C3 / 8)        // 221184
#define NP8 (CC * CC / 8)        // 73728

__global__ __launch_bounds__(256)
void prep_f16_kernel(const float* __restrict__ x,  const float* __restrict__ wa,
                     const float* __restrict__ wp,
                     __half* __restrict__ xh, __half* __restrict__ wah,
                     __half* __restrict__ wph)
{
    int i = blockIdx.x * blockDim.x + threadIdx.x;
    const float* in; __half* out;
    if (i < NX8)             { in = x;  out = xh;  }
    else if (i < NX8 + NA8)  { in = wa; out = wah; i -= NX8; }
    else if (i < NX8 + NA8 + NP8) { in = wp; out = wph; i -= NX8 + NA8; }
    else return;
    const float4 v0 = reinterpret_cast<const float4*>(in)[2*i];
    const float4 v1 = reinterpret_cast<const float4*>(in)[2*i + 1];
    __half2 h[4];
    h[0] = __floats2half2_rn(v0.x, v0.y);
    h[1] = __floats2half2_rn(v0.z, v0.w);
    h[2] = __floats2half2_rn(v1.x, v1.y);
    h[3] = __floats2half2_rn(v1.z, v1.w);
    reinterpret_cast<uint4*>(out)[i] = *reinterpret_cast<uint4*>(h);
}

// ================= fp16 tensor-core GEMM, BN=128 (QKV + proj) =================
#define BM 128
#define BN 128
#define BK 32
#define AS_STR 40
#define BS_STR 136

template <bool HALF_OUT>
__global__ __launch_bounds__(256, 2)
void h16_gemm_bias(const __half* __restrict__ A,
                   const __half* __restrict__ W,
                   const float* __restrict__ bias,
                   void* __restrict__ CoutV,
                   int M, int N, int K)
{
    __shared__ __half As[2][BM][AS_STR];
    __shared__ __half Bs[2][BK][BS_STR];

    const int tid  = threadIdx.x;
    const int lane = tid & 31;
    const int warp = tid >> 5;
    const int wm   = warp >> 2;
    const int wn   = warp & 3;
    const int grp  = lane >> 2;
    const int qd   = lane & 3;
    const int m0   = blockIdx.y * BM;
    const int n0   = blockIdx.x * BN;

    const int a_row = tid >> 2;
    const int a_col = (tid & 3) * 8;
    const int b_row = tid >> 4;
    const int b_col = (tid & 15) * 8;

    const unsigned as_base = (unsigned)__cvta_generic_to_shared(&As[0][0][0]);
    const unsigned bs_base = (unsigned)__cvta_generic_to_shared(&Bs[0][0][0]);
    const int rk_row = (lane & 7) + ((lane >> 3) & 1) * 8;
    const int rk_col = (lane >> 4) * 8;

    float acc[4][4][4] = {};

    auto load_tile = [&](int buf, int k0) {
        cp_async16(&As[buf][a_row     ][a_col], &A[(size_t)(m0 + a_row     ) * K + k0 + a_col]);
        cp_async16(&As[buf][a_row + 64][a_col], &A[(size_t)(m0 + a_row + 64) * K + k0 + a_col]);
        cp_async16(&Bs[buf][b_row     ][b_col], &W[(size_t)(k0 + b_row     ) * N + n0 + b_col]);
        cp_async16(&Bs[buf][b_row + 16][b_col], &W[(size_t)(k0 + b_row + 16) * N + n0 + b_col]);
        asm volatile("cp.async.commit_group;\n");
    };

    const int nk = K / BK;
    load_tile(0, 0);
    asm volatile("cp.async.wait_group 0;\n");
    __syncthreads();

    for (int t = 0; t < nk; t++) {
        const int buf = t & 1;
        if (t + 1 < nk) load_tile(buf ^ 1, (t + 1) * BK);

        #pragma unroll
        for (int ks = 0; ks < BK; ks += 16) {
            unsigned afr[4][4], bfr[2][4];
            #pragma unroll
            for (int mt = 0; mt < 4; mt++) {
                const unsigned addr = as_base +
                    (unsigned)(((buf * BM + wm * 64 + mt * 16 + rk_row) * AS_STR
                                + ks + rk_col) * 2);
                LDSM_X4(afr[mt], addr);
            }
            #pragma unroll
            for (int nh = 0; nh < 2; nh++) {
                const unsigned addr = bs_base +
                    (unsigned)(((buf * BK + ks + rk_row) * BS_STR
                                + wn * 32 + nh * 16 + rk_col) * 2);
                LDSM_X4_T(bfr[nh], addr);
            }
            #pragma unroll
            for (int mt = 0; mt < 4; mt++)
                #pragma unroll
                for (int nt = 0; nt < 4; nt++) {
                    const int nh = nt >> 1, lo = (nt & 1) * 2;
                    MMA_F16(acc[mt][nt], afr[mt], bfr[nh][lo], bfr[nh][lo + 1]);
                }
        }

        if (t + 1 < nk) asm volatile("cp.async.wait_group 0;\n");
        __syncthreads();
    }

    #pragma unroll
    for (int mt = 0; mt < 4; mt++) {
        const int r = m0 + wm * 64 + mt * 16 + grp;
        #pragma unroll
        for (int nt = 0; nt < 4; nt++) {
            const int c = n0 + wn * 32 + nt * 8 + qd * 2;
            const float2 bi = *reinterpret_cast<const float2*>(&bias[c]);
            const float v00 = acc[mt][nt][0] + bi.x, v01 = acc[mt][nt][1] + bi.y;
            const float v10 = acc[mt][nt][2] + bi.x, v11 = acc[mt][nt][3] + bi.y;
            if (HALF_OUT) {
                __half* Ch = (__half*)CoutV;
                *reinterpret_cast<__half2*>(&Ch[(size_t)r       * N + c]) = __floats2half2_rn(v00, v01);
                *reinterpret_cast<__half2*>(&Ch[(size_t)(r + 8) * N + c]) = __floats2half2_rn(v10, v11);
            } else {
                float* Cf = (float*)CoutV;
                *reinterpret_cast<float2*>(&Cf[(size_t)r       * N + c]) = make_float2(v00, v01);
                *reinterpret_cast<float2*>(&Cf[(size_t)(r + 8) * N + c]) = make_float2(v10, v11);
            }
        }
    }
}

// ================= fp16 flash attention: single-wave packed q-blocks =================
// grid (3, NH, BB) = 288 CTAs. Each CTA processes a list of q-blocks whose causal
// KV-tile counts sum to 24 for every CTA:
//   x=0: {7,3} -> 16+8 ; x=1: {6,4} -> 14+10 ; x=2: {5,2,1,0} -> 12+6+4+2.
// 288 CTAs <= 296 concurrent slots (occ 2) -> one uniform wave.
#define FBQ  128
#define FBKV 64
#define NQB  (TT / FBQ)    // 8
#define KS_STR 72
#define VS_STR 72
#define QS_STR 72

#define OFF_K 0
#define OFF_V (2 * FBKV * KS_STR)
#define OFF_Q (OFF_V + 2 * FBKV * VS_STR)
#define FLASH_SMEM_HALFS (OFF_Q + FBQ * QS_STR)
#define FLASH_SMEM_BYTES (FLASH_SMEM_HALFS * 2)    // 55296

#define ONES_H2 0x3C003C00u

__device__ __constant__ signed char QMAP[3][4] = {
    {7, 3, -1, -1},
    {6, 4, -1, -1},
    {5, 2, 1, 0}
};

__global__ __launch_bounds__(256)
void flash_attn_h16(const __half* __restrict__ qkv, __half* __restrict__ y)
{
    extern __shared__ __half hsm[];
    __half* KsBase = hsm + OFF_K;
    __half* VsBase = hsm + OFF_V;
    __half* Qsm    = hsm + OFF_Q;

    const int tid  = threadIdx.x;
    const int lane = tid & 31;
    const int warp = tid >> 5;
    const int g8   = lane >> 2;
    const int qd   = lane & 3;
    const int h    = blockIdx.y;
    const int b    = blockIdx.z;
    const int wb   = warp * 16;

    const unsigned k_sbase = (unsigned)__cvta_generic_to_shared(KsBase);
    const unsigned v_sbase = (unsigned)__cvta_generic_to_shared(VsBase);
    const unsigned q_sbase = (unsigned)__cvta_generic_to_shared(Qsm);

    const int rk_row = (lane & 7) + ((lane >> 3) & 1) * 8;
    const int rk_col = (lane >> 4) * 8;
    const int bn_row = (lane & 7) + (lane >> 4) * 8;
    const int bn_col = ((lane >> 3) & 1) * 8;

    const __half* base = qkv + (size_t)b * TT * C3 + h * HD;

    auto load_kv = [&](int bf, int kt) {
        const int r = tid >> 2;
        const int c = (tid & 3) * 16;
        __half* Kd = KsBase + bf * (FBKV * KS_STR);
        __half* Vd = VsBase + bf * (FBKV * VS_STR);
        const __half* rowp = base + (size_t)(kt + r) * C3;
        cp_async16(&Kd[r * KS_STR + c    ], rowp + CC   + c);
        cp_async16(&Kd[r * KS_STR + c + 8], rowp + CC   + c + 8);
        cp_async16(&Vd[r * VS_STR + c    ], rowp + 2*CC + c);
        cp_async16(&Vd[r * VS_STR + c + 8], rowp + 2*CC + c + 8);
        asm volatile("cp.async.commit_group;\n");
    };

    #pragma unroll 1
    for (int pi = 0; pi < 4; pi++) {
        const int qb = (int)QMAP[blockIdx.x][pi];
        if (qb < 0) break;
        const int q0 = qb * FBQ;

        // ---- stage Q ----
        {
            const int r = tid >> 2;
            const int c = (tid & 3) * 16;
            cp_async16(&Qsm[(r     ) * QS_STR + c    ], &base[(size_t)(q0 + r     ) * C3 + c    ]);
            cp_async16(&Qsm[(r     ) * QS_STR + c + 8], &base[(size_t)(q0 + r     ) * C3 + c + 8]);
            cp_async16(&Qsm[(r + 64) * QS_STR + c    ], &base[(size_t)(q0 + r + 64) * C3 + c    ]);
            cp_async16(&Qsm[(r + 64) * QS_STR + c + 8], &base[(size_t)(q0 + r + 64) * C3 + c + 8]);
        }

        float m_i[2] = {-1e30f, -1e30f};
        float l_i[2] = {0.f, 0.f};
        float O[8][4] = {};
        unsigned qfr[4][4];

        const int ntiles = (q0 + FBQ) / FBKV;
        load_kv(0, 0);   // commits Q staging + first K/V together

        for (int t = 0; t < ntiles; t++) {
            const int buf = t & 1;
            const int kt  = t * FBKV;
            asm volatile("cp.async.wait_group 0;\n");
            __syncthreads();

            if (t == 0) {
                const __half2 sc2 = __floats2half2_rn(0.125f, 0.125f);
                #pragma unroll
                for (int ks = 0; ks < 4; ks++) {
                    const unsigned addr = q_sbase +
                        (unsigned)(((wb + rk_row) * QS_STR + ks * 16 + rk_col) * 2);
                    LDSM_X4(qfr[ks], addr);
                    #pragma unroll
                    for (int j = 0; j < 4; j++) {
                        __half2 hv = *reinterpret_cast<__half2*>(&qfr[ks][j]);
                        hv = __hmul2(hv, sc2);
                        qfr[ks][j] = *reinterpret_cast<unsigned*>(&hv);
                    }
                }
            }
            if (t + 1 < ntiles) load_kv(buf ^ 1, kt + FBKV);

            const unsigned kb_off = k_sbase + (unsigned)(buf * (FBKV * KS_STR) * 2);
            const unsigned vb_off = v_sbase + (unsigned)(buf * (FBKV * VS_STR) * 2);

            // ---- S = Q @ K^T ----
            float scf[8][4] = {};
            #pragma unroll
            for (int ks = 0; ks < 4; ks++) {
                #pragma unroll
                for (int ntp = 0; ntp < 4; ntp++) {
                    unsigned kb[4];
                    const unsigned addr = kb_off +
                        (unsigned)(((ntp * 16 + bn_row) * KS_STR + ks * 16 + bn_col) * 2);
                    LDSM_X4(kb, addr);
                    MMA_F16(scf[2*ntp    ], qfr[ks], kb[0], kb[1]);
                    MMA_F16(scf[2*ntp + 1], qfr[ks], kb[2], kb[3]);
                }
            }

            // ---- causal mask (diagonal tiles only) ----
            if (kt + FBKV > q0) {
                const int r0g = q0 + wb + g8;
                const int r1g = r0g + 8;
                #pragma unroll
                for (int nt = 0; nt < 8; nt++) {
                    const int c0 = kt + nt * 8 + 2 * qd;
                    if (c0     > r0g) scf[nt][0] = -1e30f;
                    if (c0 + 1 > r0g) scf[nt][1] = -1e30f;
                    if (c0     > r1g) scf[nt][2] = -1e30f;
                    if (c0 + 1 > r1g) scf[nt][3] = -1e30f;
                }
            }

            // ---- row max ----
            float mx0 = -1e30f, mx1 = -1e30f;
            #pragma unroll
            for (int nt = 0; nt < 8; nt++) {
                mx0 = fmaxf(mx0, fmaxf(scf[nt][0], scf[nt][1]));
                mx1 = fmaxf(mx1, fmaxf(scf[nt][2], scf[nt][3]));
            }
            #pragma unroll
            for (int off = 1; off <= 2; off <<= 1) {
                mx0 = fmaxf(mx0, __shfl_xor_sync(0xffffffffu, mx0, off));
                mx1 = fmaxf(mx1, __shfl_xor_sync(0xffffffffu, mx1, off));
            }
            const float mn0 = fmaxf(m_i[0], mx0);
            const float mn1 = fmaxf(m_i[1], mx1);
            const float mn0L = mn0 * LOG2E;
            const float mn1L = mn1 * LOG2E;
            const float cr0 = ex2f(fmaf(m_i[0], LOG2E, -mn0L));
            const float cr1 = ex2f(fmaf(m_i[1], LOG2E, -mn1L));
            m_i[0] = mn0; m_i[1] = mn1;

            // ---- P = exp2(S·log2e − m·log2e), built DIRECTLY as PV A-fragments ----
            unsigned pfr[4][4];
            #pragma unroll
            for (int ks = 0; ks < 4; ks++) {
                pfr[ks][0] = h2ex2(pack_h2(fmaf(scf[2*ks  ][0], LOG2E, -mn0L),
                                           fmaf(scf[2*ks  ][1], LOG2E, -mn0L)));
                pfr[ks][1] = h2ex2(pack_h2(fmaf(scf[2*ks  ][2], LOG2E, -mn1L),
                                           fmaf(scf[2*ks  ][3], LOG2E, -mn1L)));
                pfr[ks][2] = h2ex2(pack_h2(fmaf(scf[2*ks+1][0], LOG2E, -mn0L),
                                           fmaf(scf[2*ks+1][1], LOG2E, -mn0L)));
                pfr[ks][3] = h2ex2(pack_h2(fmaf(scf[2*ks+1][2], LOG2E, -mn1L),
                                           fmaf(scf[2*ks+1][3], LOG2E, -mn1L)));
            }

            // ---- O *= corr ----
            #pragma unroll
            for (int nt = 0; nt < 8; nt++) {
                O[nt][0] *= cr0; O[nt][1] *= cr0;
                O[nt][2] *= cr1; O[nt][3] *= cr1;
            }

            // ---- O += P @ V ; row sums l via ones-column MMA ----
            float lacc[4] = {0.f, 0.f, 0.f, 0.f};
            #pragma unroll
            for (int ks = 0; ks < 4; ks++) {
                MMA_F16(lacc, pfr[ks], ONES_H2, ONES_H2);
                #pragma unroll
                for (int nh = 0; nh < 4; nh++) {
                    unsigned vb[4];
                    const unsigned vaddr = vb_off +
                        (unsigned)(((ks * 16 + rk_row) * VS_STR + nh * 16 + rk_col) * 2);
                    LDSM_X4_T(vb, vaddr);
                    MMA_F16(O[2*nh    ], pfr[ks], vb[0], vb[1]);
                    MMA_F16(O[2*nh + 1], pfr[ks], vb[2], vb[3]);
                }
            }
            l_i[0] = l_i[0] * cr0 + lacc[0];
            l_i[1] = l_i[1] * cr1 + lacc[2];
        }

        // ---- epilogue for this q-block ----
        const float inv0 = 1.f / l_i[0];
        const float inv1 = 1.f / l_i[1];
        const size_t r0 = (size_t)b * TT + q0 + wb + g8;
        const size_t r1 = r0 + 8;
        #pragma unroll
        for (int nt = 0; nt < 8; nt++) {
            const int c = h * HD + nt * 8 + 2 * qd;
            *reinterpret_cast<__half2*>(&y[r0 * CC + c]) =
                __floats2half2_rn(O[nt][0] * inv0, O[nt][1] * inv0);
            *reinterpret_cast<__half2*>(&y[r1 * CC + c]) =
                __floats2half2_rn(O[nt][2] * inv1, O[nt][3] * inv1);
        }

        __syncthreads();   // smem safe to reuse for next q-block
    }
}

// ---------------- launch ----------------
extern "C" void kernel_launch(void* const* d_in, const int* in_sizes, int n_in,
                              void* d_out, int out_size)
{
    const float* x      = (const float*)d_in[0];
    const float* W_attn = (const float*)d_in[1];
    const float* b_attn = (const float*)d_in[2];
    const float* W_proj = (const float*)d_in[3];
    const float* b_proj = (const float*)d_in[4];
    float* out = (float*)d_out;

    __half *qkvh, *yh, *xh, *wah, *wph;
    cudaGetSymbolAddress((void**)&qkvh, g_qkvh);
    cudaGetSymbolAddress((void**)&yh,   g_yh);
    cudaGetSymbolAddress((void**)&xh,   g_xh);
    cudaGetSymbolAddress((void**)&wah,  g_wah);
    cudaGetSymbolAddress((void**)&wph,  g_wph);

    cudaFuncSetAttribute(flash_attn_h16,
                         cudaFuncAttributeMaxDynamicSharedMemorySize,
                         FLASH_SMEM_BYTES);

    const int M = BB * TT;   // 8192

    // 0) convert inputs to fp16 (single merged launch)
    {
        const int ntot = NX8 + NA8 + NP8;
        prep_f16_kernel<<<(ntot + 255) / 256, 256>>>(x, W_attn, W_proj, xh, wah, wph);
    }
    // 1) qkv = xh @ wah + b_attn (fp16 out)
    {
        dim3 grid(C3 / BN, M / BM);        // (18, 64)
        h16_gemm_bias<true><<<grid, 256>>>(xh, wah, b_attn, qkvh, M, C3, CC);
    }
    // 2) flash attention -> yh (single-wave packed q-blocks)
    {
        dim3 grid(3, NH, BB);              // (3, 12, 8) = 288 CTAs, 24 tiles each
        flash_attn_h16<<<grid, 256, FLASH_SMEM_BYTES>>>(qkvh, yh);
    }
    // 3) out = yh @ wph + b_proj (fp32 out; reverted to BN=128)
    {
        dim3 grid(CC / BN, M / BM);        // (6, 64)
        h16_gemm_bias<false><<<grid, 256>>>(yh, wph, b_proj, out, M, CC, CC);
    }
}

// round 14
// speedup vs baseline: 1.0469x; 1.0045x over previous
#include <cuda_runtime.h>
#include <cuda_fp16.h>
#include <math.h>

// Problem constants
#define BB 8
#define TT 1024
#define CC 768
#define NH 12
#define HD 64
#define C3 (3*CC)   // 2304

#define LOG2E 1.4426950408889634f

// ---------------- scratch (no allocation allowed) ----------------
__device__ __half g_qkvh[BB * TT * C3];  // fp16 qkv
__device__ __half g_yh  [BB * TT * CC];  // fp16 attention output
__device__ __half g_xh  [BB * TT * CC];  // fp16 x
__device__ __half g_wah [CC * C3];       // fp16 W_attn
__device__ __half g_wph [CC * CC];       // fp16 W_proj

__device__ __forceinline__ void cp_async16(void* smem, const void* gmem) {
    unsigned s = (unsigned)__cvta_generic_to_shared(smem);
    asm volatile("cp.async.cg.shared.global [%0], [%1], 16;\n" :: "r"(s), "l"(gmem));
}

__device__ __forceinline__ float ex2f(float x) {
    float r; asm("ex2.approx.f32 %0, %1;" : "=f"(r) : "f"(x)); return r;
}
__device__ __forceinline__ unsigned h2ex2(unsigned x) {
    unsigned r; asm("ex2.approx.f16x2 %0, %1;" : "=r"(r) : "r"(x)); return r;
}
__device__ __forceinline__ unsigned pack_h2(float lo, float hi) {
    __half2 h = __floats2half2_rn(lo, hi);
    return *reinterpret_cast<unsigned*>(&h);
}
__device__ __forceinline__ float2 h2f2(unsigned u) {
    return __half22float2(*reinterpret_cast<__half2*>(&u));
}

#define MMA_F16(acc, a, b0v, b1v)                                               \
    asm volatile(                                                               \
        "mma.sync.aligned.m16n8k16.row.col.f32.f16.f16.f32 "                    \
        "{%0,%1,%2,%3}, {%4,%5,%6,%7}, {%8,%9}, {%0,%1,%2,%3};"                 \
        : "+f"(acc[0]), "+f"(acc[1]), "+f"(acc[2]), "+f"(acc[3])                \
        : "r"(a[0]), "r"(a[1]), "r"(a[2]), "r"(a[3]), "r"(b0v), "r"(b1v))

#define LDSM_X4(r, addr)                                                        \
    asm volatile("ldmatrix.sync.aligned.m8n8.x4.shared.b16 {%0,%1,%2,%3}, [%4];"\
        : "=r"((r)[0]), "=r"((r)[1]), "=r"((r)[2]), "=r"((r)[3]) : "r"(addr))

#define LDSM_X4_T(r, addr)                                                      \
    asm volatile("ldmatrix.sync.aligned.m8n8.x4.trans.shared.b16 {%0,%1,%2,%3}, [%4];"\
        : "=r"((r)[0]), "=r"((r)[1]), "=r"((r)[2]), "=r"((r)[3]) : "r"(addr))

// ---------------- merged pre-pass: fp32 -> fp16 for x, W_attn, W_proj ----------------
#define NX8 (BB * TT * CC / 8)   // 786432
#define NA8 (CC * C3 / 8)        // 221184
#define NP8 (CC * CC / 8)        // 73728

__global__ __launch_bounds__(256)
void prep_f16_kernel(const float* __restrict__ x,  const float* __restrict__ wa,
                     const float* __restrict__ wp,
                     __half* __restrict__ xh, __half* __restrict__ wah,
                     __half* __restrict__ wph)
{
    int i = blockIdx.x * blockDim.x + threadIdx.x;
    const float* in; __half* out;
    if (i < NX8)             { in = x;  out = xh;  }
    else if (i < NX8 + NA8)  { in = wa; out = wah; i -= NX8; }
    else if (i < NX8 + NA8 + NP8) { in = wp; out = wph; i -= NX8 + NA8; }
    else return;
    const float4 v0 = reinterpret_cast<const float4*>(in)[2*i];
    const float4 v1 = reinterpret_cast<const float4*>(in)[2*i + 1];
    __half2 h[4];
    h[0] = __floats2half2_rn(v0.x, v0.y);
    h[1] = __floats2half2_rn(v0.z, v0.w);
    h[2] = __floats2half2_rn(v1.x, v1.y);
    h[3] = __floats2half2_rn(v1.z, v1.w);
    reinterpret_cast<uint4*>(out)[i] = *reinterpret_cast<uint4*>(h);
}

// ================= fp16 tensor-core GEMM, BN=128 (QKV + proj) =================
#define BM 128
#define BN 128
#define BK 32
#define AS_STR 40
#define BS_STR 136

template <bool HALF_OUT>
__global__ __launch_bounds__(256, 2)
void h16_gemm_bias(const __half* __restrict__ A,
                   const __half* __restrict__ W,
                   const float* __restrict__ bias,
                   void* __restrict__ CoutV,
                   int M, int N, int K)
{
    __shared__ __half As[2][BM][AS_STR];
    __shared__ __half Bs[2][BK][BS_STR];

    const int tid  = threadIdx.x;
    const int lane = tid & 31;
    const int warp = tid >> 5;
    const int wm   = warp >> 2;
    const int wn   = warp & 3;
    const int grp  = lane >> 2;
    const int qd   = lane & 3;
    const int m0   = blockIdx.y * BM;
    const int n0   = blockIdx.x * BN;

    const int a_row = tid >> 2;
    const int a_col = (tid & 3) * 8;
    const int b_row = tid >> 4;
    const int b_col = (tid & 15) * 8;

    const unsigned as_base = (unsigned)__cvta_generic_to_shared(&As[0][0][0]);
    const unsigned bs_base = (unsigned)__cvta_generic_to_shared(&Bs[0][0][0]);
    const int rk_row = (lane & 7) + ((lane >> 3) & 1) * 8;
    const int rk_col = (lane >> 4) * 8;

    float acc[4][4][4] = {};

    auto load_tile = [&](int buf, int k0) {
        cp_async16(&As[buf][a_row     ][a_col], &A[(size_t)(m0 + a_row     ) * K + k0 + a_col]);
        cp_async16(&As[buf][a_row + 64][a_col], &A[(size_t)(m0 + a_row + 64) * K + k0 + a_col]);
        cp_async16(&Bs[buf][b_row     ][b_col], &W[(size_t)(k0 + b_row     ) * N + n0 + b_col]);
        cp_async16(&Bs[buf][b_row + 16][b_col], &W[(size_t)(k0 + b_row + 16) * N + n0 + b_col]);
        asm volatile("cp.async.commit_group;\n");
    };

    const int nk = K / BK;
    load_tile(0, 0);
    asm volatile("cp.async.wait_group 0;\n");
    __syncthreads();

    for (int t = 0; t < nk; t++) {
        const int buf = t & 1;
        if (t + 1 < nk) load_tile(buf ^ 1, (t + 1) * BK);

        #pragma unroll
        for (int ks = 0; ks < BK; ks += 16) {
            unsigned afr[4][4], bfr[2][4];
            #pragma unroll
            for (int mt = 0; mt < 4; mt++) {
                const unsigned addr = as_base +
                    (unsigned)(((buf * BM + wm * 64 + mt * 16 + rk_row) * AS_STR
                                + ks + rk_col) * 2);
                LDSM_X4(afr[mt], addr);
            }
            #pragma unroll
            for (int nh = 0; nh < 2; nh++) {
                const unsigned addr = bs_base +
                    (unsigned)(((buf * BK + ks + rk_row) * BS_STR
                                + wn * 32 + nh * 16 + rk_col) * 2);
                LDSM_X4_T(bfr[nh], addr);
            }
            #pragma unroll
            for (int mt = 0; mt < 4; mt++)
                #pragma unroll
                for (int nt = 0; nt < 4; nt++) {
                    const int nh = nt >> 1, lo = (nt & 1) * 2;
                    MMA_F16(acc[mt][nt], afr[mt], bfr[nh][lo], bfr[nh][lo + 1]);
                }
        }

        if (t + 1 < nk) asm volatile("cp.async.wait_group 0;\n");
        __syncthreads();
    }

    #pragma unroll
    for (int mt = 0; mt < 4; mt++) {
        const int r = m0 + wm * 64 + mt * 16 + grp;
        #pragma unroll
        for (int nt = 0; nt < 4; nt++) {
            const int c = n0 + wn * 32 + nt * 8 + qd * 2;
            const float2 bi = *reinterpret_cast<const float2*>(&bias[c]);
            const float v00 = acc[mt][nt][0] + bi.x, v01 = acc[mt][nt][1] + bi.y;
            const float v10 = acc[mt][nt][2] + bi.x, v11 = acc[mt][nt][3] + bi.y;
            if (HALF_OUT) {
                __half* Ch = (__half*)CoutV;
                *reinterpret_cast<__half2*>(&Ch[(size_t)r       * N + c]) = __floats2half2_rn(v00, v01);
                *reinterpret_cast<__half2*>(&Ch[(size_t)(r + 8) * N + c]) = __floats2half2_rn(v10, v11);
            } else {
                float* Cf = (float*)CoutV;
                *reinterpret_cast<float2*>(&Cf[(size_t)r       * N + c]) = make_float2(v00, v01);
                *reinterpret_cast<float2*>(&Cf[(size_t)(r + 8) * N + c]) = make_float2(v10, v11);
            }
        }
    }
}

// ================= fp16 flash attention: single-wave packed q-blocks =================
// grid (3, NH, BB) = 288 CTAs, 24 KV tiles each. Fully-masked half-tiles skipped
// per-warp (bit-exact). l via fp32 sum of the same fp16 P fragments used in PV.
#define FBQ  128
#define FBKV 64
#define NQB  (TT / FBQ)    // 8
#define KS_STR 72
#define VS_STR 72
#define QS_STR 72

#define OFF_K 0
#define OFF_V (2 * FBKV * KS_STR)
#define OFF_Q (OFF_V + 2 * FBKV * VS_STR)
#define FLASH_SMEM_HALFS (OFF_Q + FBQ * QS_STR)
#define FLASH_SMEM_BYTES (FLASH_SMEM_HALFS * 2)    // 55296

__device__ __constant__ signed char QMAP[3][4] = {
    {7, 3, -1, -1},
    {6, 4, -1, -1},
    {5, 2, 1, 0}
};

__global__ __launch_bounds__(256)
void flash_attn_h16(const __half* __restrict__ qkv, __half* __restrict__ y)
{
    extern __shared__ __half hsm[];
    __half* KsBase = hsm + OFF_K;
    __half* VsBase = hsm + OFF_V;
    __half* Qsm    = hsm + OFF_Q;

    const int tid  = threadIdx.x;
    const int lane = tid & 31;
    const int warp = tid >> 5;
    const int g8   = lane >> 2;
    const int qd   = lane & 3;
    const int h    = blockIdx.y;
    const int b    = blockIdx.z;
    const int wb   = warp * 16;

    const unsigned k_sbase = (unsigned)__cvta_generic_to_shared(KsBase);
    const unsigned v_sbase = (unsigned)__cvta_generic_to_shared(VsBase);
    const unsigned q_sbase = (unsigned)__cvta_generic_to_shared(Qsm);

    const int rk_row = (lane & 7) + ((lane >> 3) & 1) * 8;
    const int rk_col = (lane >> 4) * 8;
    const int bn_row = (lane & 7) + (lane >> 4) * 8;
    const int bn_col = ((lane >> 3) & 1) * 8;

    const __half* base = qkv + (size_t)b * TT * C3 + h * HD;

    auto load_kv = [&](int bf, int kt) {
        const int r = tid >> 2;
        const int c = (tid & 3) * 16;
        __half* Kd = KsBase + bf * (FBKV * KS_STR);
        __half* Vd = VsBase + bf * (FBKV * VS_STR);
        const __half* rowp = base + (size_t)(kt + r) * C3;
        cp_async16(&Kd[r * KS_STR + c    ], rowp + CC   + c);
        cp_async16(&Kd[r * KS_STR + c + 8], rowp + CC   + c + 8);
        cp_async16(&Vd[r * VS_STR + c    ], rowp + 2*CC + c);
        cp_async16(&Vd[r * VS_STR + c + 8], rowp + 2*CC + c + 8);
        asm volatile("cp.async.commit_group;\n");
    };

    #pragma unroll 1
    for (int pi = 0; pi < 4; pi++) {
        const int qb = (int)QMAP[blockIdx.x][pi];
        if (qb < 0) break;
        const int q0 = qb * FBQ;

        // ---- stage Q ----
        {
            const int r = tid >> 2;
            const int c = (tid & 3) * 16;
            cp_async16(&Qsm[(r     ) * QS_STR + c    ], &base[(size_t)(q0 + r     ) * C3 + c    ]);
            cp_async16(&Qsm[(r     ) * QS_STR + c + 8], &base[(size_t)(q0 + r     ) * C3 + c + 8]);
            cp_async16(&Qsm[(r + 64) * QS_STR + c    ], &base[(size_t)(q0 + r + 64) * C3 + c    ]);
            cp_async16(&Qsm[(r + 64) * QS_STR + c + 8], &base[(size_t)(q0 + r + 64) * C3 + c + 8]);
        }

        float m_i[2] = {-1e30f, -1e30f};
        float l_i[2] = {0.f, 0.f};
        float O[8][4] = {};
        unsigned qfr[4][4];

        const int ntiles = (q0 + FBQ) / FBKV;
        load_kv(0, 0);   // commits Q staging + first K/V together

        for (int t = 0; t < ntiles; t++) {
            const int buf = t & 1;
            const int kt  = t * FBKV;
            asm volatile("cp.async.wait_group 0;\n");
            __syncthreads();

            if (t == 0) {
                const __half2 sc2 = __floats2half2_rn(0.125f, 0.125f);
                #pragma unroll
                for (int ks = 0; ks < 4; ks++) {
                    const unsigned addr = q_sbase +
                        (unsigned)(((wb + rk_row) * QS_STR + ks * 16 + rk_col) * 2);
                    LDSM_X4(qfr[ks], addr);
                    #pragma unroll
                    for (int j = 0; j < 4; j++) {
                        __half2 hv = *reinterpret_cast<__half2*>(&qfr[ks][j]);
                        hv = __hmul2(hv, sc2);
                        qfr[ks][j] = *reinterpret_cast<unsigned*>(&hv);
                    }
                }
            }
            if (t + 1 < ntiles) load_kv(buf ^ 1, kt + FBKV);

            // Fully-masked half-tile: all of this warp's rows (<= q0+wb+15) are
            // below every column of this tile -> S all masked -> corr=1, P=0.
            // Skipping is bit-exact. (No cross-warp ops inside the guarded block.)
            if (kt > q0 + wb + 15) continue;

            const unsigned kb_off = k_sbase + (unsigned)(buf * (FBKV * KS_STR) * 2);
            const unsigned vb_off = v_sbase + (unsigned)(buf * (FBKV * VS_STR) * 2);

            // ---- S = Q @ K^T ----
            float scf[8][4] = {};
            #pragma unroll
            for (int ks = 0; ks < 4; ks++) {
                #pragma unroll
                for (int ntp = 0; ntp < 4; ntp++) {
                    unsigned kb[4];
                    const unsigned addr = kb_off +
                        (unsigned)(((ntp * 16 + bn_row) * KS_STR + ks * 16 + bn_col) * 2);
                    LDSM_X4(kb, addr);
                    MMA_F16(scf[2*ntp    ], qfr[ks], kb[0], kb[1]);
                    MMA_F16(scf[2*ntp + 1], qfr[ks], kb[2], kb[3]);
                }
            }

            // ---- causal mask (diagonal tiles only) ----
            if (kt + FBKV > q0) {
                const int r0g = q0 + wb + g8;
                const int r1g = r0g + 8;
                #pragma unroll
                for (int nt = 0; nt < 8; nt++) {
                    const int c0 = kt + nt * 8 + 2 * qd;
                    if (c0     > r0g) scf[nt][0] = -1e30f;
                    if (c0 + 1 > r0g) scf[nt][1] = -1e30f;
                    if (c0     > r1g) scf[nt][2] = -1e30f;
                    if (c0 + 1 > r1g) scf[nt][3] = -1e30f;
                }
            }

            // ---- row max ----
            float mx0 = -1e30f, mx1 = -1e30f;
            #pragma unroll
            for (int nt = 0; nt < 8; nt++) {
                mx0 = fmaxf(mx0, fmaxf(scf[nt][0], scf[nt][1]));
                mx1 = fmaxf(mx1, fmaxf(scf[nt][2], scf[nt][3]));
            }
            #pragma unroll
            for (int off = 1; off <= 2; off <<= 1) {
                mx0 = fmaxf(mx0, __shfl_xor_sync(0xffffffffu, mx0, off));
                mx1 = fmaxf(mx1, __shfl_xor_sync(0xffffffffu, mx1, off));
            }
            const float mn0 = fmaxf(m_i[0], mx0);
            const float mn1 = fmaxf(m_i[1], mx1);
            const float mn0L = mn0 * LOG2E;
            const float mn1L = mn1 * LOG2E;
            const float cr0 = ex2f(fmaf(m_i[0], LOG2E, -mn0L));
            const float cr1 = ex2f(fmaf(m_i[1], LOG2E, -mn1L));
            m_i[0] = mn0; m_i[1] = mn1;

            // ---- P = exp2(S·log2e − m·log2e), built DIRECTLY as PV A-fragments ----
            unsigned pfr[4][4];
            #pragma unroll
            for (int ks = 0; ks < 4; ks++) {
                pfr[ks][0] = h2ex2(pack_h2(fmaf(scf[2*ks  ][0], LOG2E, -mn0L),
                                           fmaf(scf[2*ks  ][1], LOG2E, -mn0L)));
                pfr[ks][1] = h2ex2(pack_h2(fmaf(scf[2*ks  ][2], LOG2E, -mn1L),
                                           fmaf(scf[2*ks  ][3], LOG2E, -mn1L)));
                pfr[ks][2] = h2ex2(pack_h2(fmaf(scf[2*ks+1][0], LOG2E, -mn0L),
                                           fmaf(scf[2*ks+1][1], LOG2E, -mn0L)));
                pfr[ks][3] = h2ex2(pack_h2(fmaf(scf[2*ks+1][2], LOG2E, -mn1L),
                                           fmaf(scf[2*ks+1][3], LOG2E, -mn1L)));
            }

            // ---- partial row sums (fp32, off the tensor pipe) ----
            float rs0 = 0.f, rs1 = 0.f;
            #pragma unroll
            for (int ks = 0; ks < 4; ks++) {
                const float2 f0 = h2f2(pfr[ks][0]);
                const float2 f1 = h2f2(pfr[ks][1]);
                const float2 f2 = h2f2(pfr[ks][2]);
                const float2 f3 = h2f2(pfr[ks][3]);
                rs0 += (f0.x + f0.y) + (f2.x + f2.y);
                rs1 += (f1.x + f1.y) + (f3.x + f3.y);
            }

            // ---- O *= corr ----
            #pragma unroll
            for (int nt = 0; nt < 8; nt++) {
                O[nt][0] *= cr0; O[nt][1] *= cr0;
                O[nt][2] *= cr1; O[nt][3] *= cr1;
            }

            // ---- O += P @ V ----
            #pragma unroll
            for (int ks = 0; ks < 4; ks++) {
                #pragma unroll
                for (int nh = 0; nh < 4; nh++) {
                    unsigned vb[4];
                    const unsigned vaddr = vb_off +
                        (unsigned)(((ks * 16 + rk_row) * VS_STR + nh * 16 + rk_col) * 2);
                    LDSM_X4_T(vb, vaddr);
                    MMA_F16(O[2*nh    ], pfr[ks], vb[0], vb[1]);
                    MMA_F16(O[2*nh + 1], pfr[ks], vb[2], vb[3]);
                }
            }
            // ---- l update (lane-reduce across the 4 qd lanes) ----
            #pragma unroll
            for (int off = 1; off <= 2; off <<= 1) {
                rs0 += __shfl_xor_sync(0xffffffffu, rs0, off);
                rs1 += __shfl_xor_sync(0xffffffffu, rs1, off);
            }
            l_i[0] = l_i[0] * cr0 + rs0;
            l_i[1] = l_i[1] * cr1 + rs1;
        }

        // ---- epilogue for this q-block ----
        const float inv0 = 1.f / l_i[0];
        const float inv1 = 1.f / l_i[1];
        const size_t r0 = (size_t)b * TT + q0 + wb + g8;
        const size_t r1 = r0 + 8;
        #pragma unroll
        for (int nt = 0; nt < 8; nt++) {
            const int c = h * HD + nt * 8 + 2 * qd;
            *reinterpret_cast<__half2*>(&y[r0 * CC + c]) =
                __floats2half2_rn(O[nt][0] * inv0, O[nt][1] * inv0);
            *reinterpret_cast<__half2*>(&y[r1 * CC + c]) =
                __floats2half2_rn(O[nt][2] * inv1, O[nt][3] * inv1);
        }

        __syncthreads();   // smem safe to reuse for next q-block
    }
}

// ---------------- launch ----------------
extern "C" void kernel_launch(void* const* d_in, const int* in_sizes, int n_in,
                              void* d_out, int out_size)
{
    const float* x      = (const float*)d_in[0];
    const float* W_attn = (const float*)d_in[1];
    const float* b_attn = (const float*)d_in[2];
    const float* W_proj = (const float*)d_in[3];
    const float* b_proj = (const float*)d_in[4];
    float* out = (float*)d_out;

    __half *qkvh, *yh, *xh, *wah, *wph;
    cudaGetSymbolAddress((void**)&qkvh, g_qkvh);
    cudaGetSymbolAddress((void**)&yh,   g_yh);
    cudaGetSymbolAddress((void**)&xh,   g_xh);
    cudaGetSymbolAddress((void**)&wah,  g_wah);
    cudaGetSymbolAddress((void**)&wph,  g_wph);

    cudaFuncSetAttribute(flash_attn_h16,
                         cudaFuncAttributeMaxDynamicSharedMemorySize,
                         FLASH_SMEM_BYTES);

    const int M = BB * TT;   // 8192

    // 0) convert inputs to fp16 (single merged launch)
    {
        const int ntot = NX8 + NA8 + NP8;
        prep_f16_kernel<<<(ntot + 255) / 256, 256>>>(x, W_attn, W_proj, xh, wah, wph);
    }
    // 1) qkv = xh @ wah + b_attn (fp16 out)
    {
        dim3 grid(C3 / BN, M / BM);        // (18, 64)
        h16_gemm_bias<true><<<grid, 256>>>(xh, wah, b_attn, qkvh, M, C3, CC);
    }
    // 2) flash attention -> yh (single-wave packed q-blocks, masked-tile skip)
    {
        dim3 grid(3, NH, BB);              // (3, 12, 8) = 288 CTAs
        flash_attn_h16<<<grid, 256, FLASH_SMEM_BYTES>>>(qkvh, yh);
    }
    // 3) out = yh @ wph + b_proj (fp32 out)
    {
        dim3 grid(CC / BN, M / BM);        // (6, 64)
        h16_gemm_bias<false><<<grid, 256>>>(yh, wph, b_proj, out, M, CC, CC);
    }
}